// round 15
// baseline (speedup 1.0000x reference)
#include <cuda_runtime.h>
#include <cuda_fp16.h>
#include <math_constants.h>
#include <cstdint>

// Problem constants
#define B 16
#define S 8192
#define D 256
#define D2 512
#define NTOK (B * S)          // 131072 tokens
#define MTILE 128             // tokens per score CTA
#define KHALF 128             // k per CTA (half of D)
#define SCHUNKS 16
#define SCHUNK (S / SCHUNKS)  // 512
#define NPART (SCHUNKS * 4)   // 64 partials per batch

// ---------------------------------------------------------------------------
// Device scratch
// ---------------------------------------------------------------------------
__device__ __align__(16) __half g_Bhi[D * D];   // M^T fp16, n-major
__device__ float g_vec[2 * D + 1];      // c1[256], c2[256], c0
__device__ float g_ps[2 * NTOK];        // partial scores (k-half 0, 1)
__device__ __align__(16) float g_wpart[B * NPART * D2];   // 2 MB
// d_out layout: [output: B*2D][weights: B*S]

// ---------------------------------------------------------------------------
// Helpers
// ---------------------------------------------------------------------------
__device__ __forceinline__ uint32_t smem_u32(const void* p) {
    uint32_t a;
    asm("{ .reg .u64 t; cvta.to.shared.u64 t, %1; cvt.u32.u64 %0, t; }"
        : "=r"(a) : "l"(p));
    return a;
}
__device__ __forceinline__ void cp_async16(uint32_t dst, const void* src) {
    asm volatile("cp.async.ca.shared.global [%0], [%1], 16;"
                 :: "r"(dst), "l"(src) : "memory");
}
__device__ __forceinline__ void ldsm_x4(uint32_t* r, uint32_t addr) {
    asm volatile("ldmatrix.sync.aligned.m8n8.x4.shared.b16 {%0,%1,%2,%3}, [%4];"
                 : "=r"(r[0]), "=r"(r[1]), "=r"(r[2]), "=r"(r[3]) : "r"(addr));
}
__device__ __forceinline__ void mma16816(float* d, const uint32_t* a,
                                         uint32_t b0, uint32_t b1) {
    asm("mma.sync.aligned.m16n8k16.row.col.f32.f16.f16.f32 "
        "{%0,%1,%2,%3}, {%4,%5,%6,%7}, {%8,%9}, {%0,%1,%2,%3};"
        : "+f"(d[0]), "+f"(d[1]), "+f"(d[2]), "+f"(d[3])
        : "r"(a[0]), "r"(a[1]), "r"(a[2]), "r"(a[3]), "r"(b0), "r"(b1));
}

// ---------------------------------------------------------------------------
// Prep (fused): Bmat[n][k] = M[k][n] = Wq[k,:]·Wk[n,:] -> fp16, n-major.
// Block (0,0) additionally computes c1/c2/c0.
// ---------------------------------------------------------------------------
__global__ void prep_kernel(const float* __restrict__ wq, const float* __restrict__ wk,
                            const float* __restrict__ bq, const float* __restrict__ bk) {
    __shared__ float aS[16][16];
    __shared__ float bS[16][17];
    int tx = threadIdx.x, ty = threadIdx.y;
    int i = blockIdx.y * 16 + ty;   // k index
    int j = blockIdx.x * 16 + tx;   // n index
    float acc = 0.f;
    for (int kt = 0; kt < D; kt += 16) {
        aS[ty][tx] = wq[(blockIdx.y * 16 + ty) * D + kt + tx];
        bS[ty][tx] = wk[(blockIdx.x * 16 + ty) * D + kt + tx];
        __syncthreads();
#pragma unroll
        for (int kk = 0; kk < 16; kk++)
            acc = fmaf(aS[ty][kk], bS[tx][kk], acc);
        __syncthreads();
    }
    g_Bhi[j * D + i] = __float2half_rn(acc);

    if (blockIdx.x == 0 && blockIdx.y == 0) {
        int t = ty * 16 + tx;      // 0..255
        float s1 = 0.f, s2 = 0.f;
#pragma unroll 4
        for (int k = 0; k < D; k++) {
            s1 = fmaf(wq[t * D + k], bk[k], s1);
            s2 = fmaf(wk[t * D + k], bq[k], s2);
        }
        g_vec[t] = s1;
        g_vec[D + t] = s2;
        if (t == 0) {
            float c0 = 0.f;
            for (int k = 0; k < D; k++) c0 = fmaf(bq[k], bk[k], c0);
            g_vec[2 * D] = c0;
        }
    }
}

// ---------------------------------------------------------------------------
// Probe: no-op; positions score_kernel at the ncu capture slot (4th launch).
// ---------------------------------------------------------------------------
__global__ void probe_kernel() {}

// ---------------------------------------------------------------------------
// Score kernel, k-split for 2 CTAs/SM: grid (1024, 2). CTA = 128 tokens x
// 128 k-half. 256 threads, 8 warps (2m x 4n), warp = 64 rows x 64 cols,
// acc[4][8][4] = 128 regs (launch_bounds(256,2) pins 128).
// Dyn smem: A [128 x 272B] + B [256 x 272B] = 104448 -> 2 CTAs/SM.
// Phase overlap: one CTA's mainloop hides the other's DRAM phases.
// ---------------------------------------------------------------------------
#define A_PITCH 272
#define B_PITCH 272
#define SM_A 0
#define SM_B (128 * A_PITCH)                   // 34816
#define DSMEM_BYTES (SM_B + 256 * B_PITCH)     // 104448

__global__ __launch_bounds__(256, 2) void score_kernel(const float* __restrict__ vi,
                                                       const float* __restrict__ au) {
    extern __shared__ __align__(16) char dsm[];
    __shared__ float c1h[KHALF];
    __shared__ float c2_s[D];
    __shared__ float bpart[256];
    __shared__ float spart[4][128];

    const int tid = threadIdx.x;
    const int lane = tid & 31;
    const int w = tid >> 5;
    const int mbase = (w & 1) * 64;        // m-group: 64 rows
    const int ng = w >> 1;                 // n-group 0..3 (64 cols each)
    const int tok0 = blockIdx.x * MTILE;
    const int kh = blockIdx.y;             // k-half 0/1
    const uint32_t sbase = smem_u32(dsm);

    if (tid < 128) c1h[tid] = g_vec[kh * KHALF + tid];
    c2_s[tid] = (kh == 0) ? g_vec[D + tid] : 0.f;
    __syncthreads();

    // ---- Stage B half (M^T fp16 rows, k-half slice) via cp.async
#pragma unroll
    for (int i = 0; i < 16; i++) {
        int idx = tid + i * 256;           // 0..4095 (16B segments)
        int row = idx >> 4, seg = idx & 15;
        cp_async16(sbase + SM_B + row * B_PITCH + seg * 16,
                   g_Bhi + row * D + kh * KHALF + seg * 8);
    }
    asm volatile("cp.async.commit_group;" ::: "memory");

    // ---- Convert vi k-half to fp16 in smem (overlaps cp.async); fold vi·c1
    {
        const int r = tid >> 1;            // token row 0..127
        const int kq = (tid & 1) * 64;     // offset within k-half
        const float* vrow = vi + (size_t)(tok0 + r) * D + kh * KHALF + kq;
        char* da = dsm + SM_A + r * A_PITCH + kq * 2;
        float bs = 0.f;
#pragma unroll 2
        for (int k8 = 0; k8 < 64; k8 += 8) {
            float4 v0 = *(const float4*)(vrow + k8);
            float4 v1 = *(const float4*)(vrow + k8 + 4);
            float vv[8] = {v0.x, v0.y, v0.z, v0.w, v1.x, v1.y, v1.z, v1.w};
            uint32_t hw[4];
#pragma unroll
            for (int u = 0; u < 4; u++) {
                float a = vv[2 * u], bvl = vv[2 * u + 1];
                bs = fmaf(a, c1h[kq + k8 + 2 * u], bs);
                bs = fmaf(bvl, c1h[kq + k8 + 2 * u + 1], bs);
                __half2 hp;
                hp.x = __float2half_rn(a);
                hp.y = __float2half_rn(bvl);
                hw[u] = *(uint32_t*)&hp;
            }
            *(uint4*)(da + k8 * 2) = make_uint4(hw[0], hw[1], hw[2], hw[3]);
        }
        bpart[tid] = bs;
    }
    asm volatile("cp.async.wait_group 0;" ::: "memory");
    __syncthreads();

    // ---- ldmatrix lane addressing
    const uint32_t a_lane = (uint32_t)((lane & 15) * A_PITCH + ((lane >> 4) << 4));
    const uint32_t aA = sbase + SM_A + mbase * A_PITCH + a_lane;
    const uint32_t b_lane =
        (uint32_t)(((lane & 7) + ((lane >> 4) << 3)) * B_PITCH + ((lane & 8) ? 16 : 0));
    const uint32_t bB = sbase + SM_B + ng * 64 * B_PITCH + b_lane;

    float acc[4][8][4] = {};

    // ---- Mainloop: 8 k-steps, 8 LDSM -> 32 MMA per step
#pragma unroll
    for (int ks = 0; ks < 8; ks++) {
        const uint32_t ka = (uint32_t)(ks * 32);   // byte offset (16 k fp16)
        uint32_t ah[4][4];
#pragma unroll
        for (int mt = 0; mt < 4; mt++)
            ldsm_x4(ah[mt], aA + mt * 16 * A_PITCH + ka);
#pragma unroll
        for (int nt2 = 0; nt2 < 4; nt2++) {
            const uint32_t bo = (uint32_t)(nt2 * 16 * B_PITCH) + ka;
            uint32_t b4[4];
            ldsm_x4(b4, bB + bo);
#pragma unroll
            for (int sub = 0; sub < 2; sub++) {
                const int nt = nt2 * 2 + sub;
                const uint32_t b0 = b4[2 * sub], b1 = b4[2 * sub + 1];
#pragma unroll
                for (int mt = 0; mt < 4; mt++)
                    mma16816(acc[mt][nt], ah[mt], b0, b1);
            }
        }
    }

    // ---- Epilogue: part[t] = sum_n (Q'h[t][n] + c2h[n]) * au[t][n]
    float prow[4][2] = {};
#pragma unroll
    for (int mt = 0; mt < 4; mt++) {
        const float* au0 = au + (size_t)(tok0 + mbase + mt * 16 + (lane >> 2)) * D;
        const float* au1 = au0 + 8 * D;
#pragma unroll
        for (int nt = 0; nt < 8; nt++) {
            const int n = ng * 64 + nt * 8 + (lane & 3) * 2;
            const float2 c2v = *(const float2*)&c2_s[n];
            const float2 x0 = __ldg((const float2*)(au0 + n));
            const float2 x1 = __ldg((const float2*)(au1 + n));
            prow[mt][0] = fmaf(acc[mt][nt][0] + c2v.x, x0.x, prow[mt][0]);
            prow[mt][0] = fmaf(acc[mt][nt][1] + c2v.y, x0.y, prow[mt][0]);
            prow[mt][1] = fmaf(acc[mt][nt][2] + c2v.x, x1.x, prow[mt][1]);
            prow[mt][1] = fmaf(acc[mt][nt][3] + c2v.y, x1.y, prow[mt][1]);
        }
    }
#pragma unroll
    for (int mt = 0; mt < 4; mt++)
#pragma unroll
        for (int j = 0; j < 2; j++) {
            float v = prow[mt][j];
            v += __shfl_xor_sync(0xffffffffu, v, 1);
            v += __shfl_xor_sync(0xffffffffu, v, 2);
            if ((lane & 3) == 0)
                spart[ng][mbase + mt * 16 + j * 8 + (lane >> 2)] = v;
        }
    __syncthreads();

    if (tid < 128) {
        const float cc0 = (kh == 0) ? g_vec[2 * D] : 0.f;
        float s = (spart[0][tid] + spart[1][tid]) + (spart[2][tid] + spart[3][tid])
                + (bpart[2 * tid] + bpart[2 * tid + 1])
                + cc0;
        g_ps[kh * NTOK + tok0 + tid] = s;   // raw partial (scaled in softmax)
    }
}

// ---------------------------------------------------------------------------
// Softmax over S per batch; sums the two k-half partials, scales by 1/16.
// ---------------------------------------------------------------------------
__global__ __launch_bounds__(1024) void softmax_kernel(float* __restrict__ out) {
    __shared__ float red[32];
    __shared__ float sh_val;
    const int b = blockIdx.x;
    const int tid = threadIdx.x;
    const int lane = tid & 31, warp = tid >> 5;
    const float* p0 = g_ps + b * S;
    const float* p1 = g_ps + NTOK + b * S;
    float* w = out + B * D2 + b * S;

    float v[8];
    float mx = -CUDART_INF_F;
#pragma unroll
    for (int i = 0; i < 8; i++) {
        int idx = tid + i * 1024;
        v[i] = (p0[idx] + p1[idx]) * 0.0625f;   // 1/sqrt(256)
        mx = fmaxf(mx, v[i]);
    }
#pragma unroll
    for (int o = 16; o > 0; o >>= 1) mx = fmaxf(mx, __shfl_xor_sync(0xffffffffu, mx, o));
    if (lane == 0) red[warp] = mx;
    __syncthreads();
    if (warp == 0) {
        float m = red[lane];
#pragma unroll
        for (int o = 16; o > 0; o >>= 1) m = fmaxf(m, __shfl_xor_sync(0xffffffffu, m, o));
        if (lane == 0) sh_val = m;
    }
    __syncthreads();
    mx = sh_val;

    float sum = 0.f;
#pragma unroll
    for (int i = 0; i < 8; i++) {
        v[i] = expf(v[i] - mx);
        sum += v[i];
    }
#pragma unroll
    for (int o = 16; o > 0; o >>= 1) sum += __shfl_xor_sync(0xffffffffu, sum, o);
    if (lane == 0) red[warp] = sum;
    __syncthreads();
    if (warp == 0) {
        float s2 = red[lane];
#pragma unroll
        for (int o = 16; o > 0; o >>= 1) s2 += __shfl_xor_sync(0xffffffffu, s2, o);
        if (lane == 0) sh_val = s2;
    }
    __syncthreads();
    const float inv = 1.f / sh_val;
#pragma unroll
    for (int i = 0; i < 8; i++) w[tid + i * 1024] = v[i] * inv;
}

// ---------------------------------------------------------------------------
// Weighted sum of cat(vi, au): float4 per thread, 4-way S-split, 8-deep unroll.
// ---------------------------------------------------------------------------
__global__ __launch_bounds__(512) void wsum_kernel(const float* __restrict__ vi,
                                                   const float* __restrict__ au,
                                                   const float* __restrict__ out) {
    const int chunk = blockIdx.x;
    const int b = blockIdx.y;
    const int tid = threadIdx.x;
    const int e4 = tid & 127;
    const int sg = tid >> 7;               // 0..3
    const int e = e4 * 4;
    const long row0 = (long)b * S + chunk * SCHUNK + sg * 128;
    const float* w = out + B * D2 + b * S + chunk * SCHUNK + sg * 128;
    const float* src = (e < D) ? (vi + row0 * D + e)
                               : (au + row0 * D + (e - D));
    float4 sa[8];
#pragma unroll
    for (int i = 0; i < 8; i++) sa[i] = make_float4(0.f, 0.f, 0.f, 0.f);
#pragma unroll 1
    for (int s = 0; s < 128; s += 8) {
        float4 vld[8];
        float wl[8];
#pragma unroll
        for (int i = 0; i < 8; i++)
            vld[i] = *(const float4*)(src + (size_t)(s + i) * D);
#pragma unroll
        for (int i = 0; i < 8; i++) wl[i] = w[s + i];
#pragma unroll
        for (int i = 0; i < 8; i++) {
            sa[i].x = fmaf(wl[i], vld[i].x, sa[i].x);
            sa[i].y = fmaf(wl[i], vld[i].y, sa[i].y);
            sa[i].z = fmaf(wl[i], vld[i].z, sa[i].z);
            sa[i].w = fmaf(wl[i], vld[i].w, sa[i].w);
        }
    }
    float4 r;
    r.x = ((sa[0].x + sa[1].x) + (sa[2].x + sa[3].x))
        + ((sa[4].x + sa[5].x) + (sa[6].x + sa[7].x));
    r.y = ((sa[0].y + sa[1].y) + (sa[2].y + sa[3].y))
        + ((sa[4].y + sa[5].y) + (sa[6].y + sa[7].y));
    r.z = ((sa[0].z + sa[1].z) + (sa[2].z + sa[3].z))
        + ((sa[4].z + sa[5].z) + (sa[6].z + sa[7].z));
    r.w = ((sa[0].w + sa[1].w) + (sa[2].w + sa[3].w))
        + ((sa[4].w + sa[5].w) + (sa[6].w + sa[7].w));
    *(float4*)(g_wpart + (size_t)(b * NPART + chunk * 4 + sg) * D2 + e) = r;
}

// ---------------------------------------------------------------------------
// Final: wcat = sum of partials; output = wcat @ Wv + bv.
// Grid (B, 4): block owns 128 e-cols; threads split f into 4 segments.
// ---------------------------------------------------------------------------
__global__ __launch_bounds__(512) void out_kernel(const float* __restrict__ wv_w,
                                                  const float* __restrict__ wv_b,
                                                  float* __restrict__ out) {
    __shared__ float wc[D2];
    __shared__ float red[4][128];
    const int b = blockIdx.x;
    const int ebase = blockIdx.y * 128;
    const int tid = threadIdx.x;

    float a = 0.f;
#pragma unroll 8
    for (int c = 0; c < NPART; c++) a += g_wpart[(size_t)(b * NPART + c) * D2 + tid];
    wc[tid] = a;
    __syncthreads();

    const int e = ebase + (tid & 127);
    const int fs = tid >> 7;               // f-segment 0..3
    float o = 0.f;
#pragma unroll 4
    for (int f = fs * 128; f < fs * 128 + 128; f++)
        o = fmaf(wc[f], wv_w[f * D2 + e], o);
    red[fs][tid & 127] = o;
    __syncthreads();
    if (tid < 128) {
        out[b * D2 + ebase + tid] =
            (red[0][tid] + red[1][tid]) + (red[2][tid] + red[3][tid])
            + wv_b[ebase + tid];
    }
}

// ---------------------------------------------------------------------------
extern "C" void kernel_launch(void* const* d_in, const int* in_sizes, int n_in,
                              void* d_out, int out_size) {
    const float* au   = (const float*)d_in[0];
    const float* vi   = (const float*)d_in[1];
    const float* wq_w = (const float*)d_in[2];
    const float* wq_b = (const float*)d_in[3];
    const float* wk_w = (const float*)d_in[4];
    const float* wk_b = (const float*)d_in[5];
    const float* wv_w = (const float*)d_in[6];
    const float* wv_b = (const float*)d_in[7];
    float* out = (float*)d_out;

    static int smem_set = 0;
    if (!smem_set) {
        cudaFuncSetAttribute(score_kernel, cudaFuncAttributeMaxDynamicSharedMemorySize,
                             DSMEM_BYTES);
        smem_set = 1;
    }

    prep_kernel<<<dim3(16, 16), dim3(16, 16)>>>(wq_w, wk_w, wq_b, wk_b);
    probe_kernel<<<1, 32>>>();
    probe_kernel<<<1, 32>>>();
    score_kernel<<<dim3(NTOK / MTILE, 2), 256, DSMEM_BYTES>>>(vi, au);  // 4th -> ncu
    softmax_kernel<<<B, 1024>>>(out);
    wsum_kernel<<<dim3(SCHUNKS, B), 512>>>(vi, au, out);
    out_kernel<<<dim3(B, 4), 512>>>(wv_w, wv_b, out);
}

// round 16
// speedup vs baseline: 1.5402x; 1.5402x over previous
#include <cuda_runtime.h>
#include <cuda_fp16.h>
#include <math_constants.h>
#include <cstdint>

// Problem constants
#define B 16
#define S 8192
#define D 256
#define D2 512
#define NTOK (B * S)          // 131072 tokens
#define MTILE 128             // tokens per score CTA
#define SCHUNKS 16
#define SCHUNK (S / SCHUNKS)  // 512
#define NPART (SCHUNKS * 4)   // 64 partials per batch

// ---------------------------------------------------------------------------
// Device scratch
// ---------------------------------------------------------------------------
__device__ __align__(16) __half g_Bhi[D * D];   // M^T fp16, n-major
__device__ float g_vec[2 * D + 1];      // c1[256], c2[256], c0
__device__ float g_score[NTOK];
__device__ __align__(16) float g_wpart[B * NPART * D2];   // 2 MB
// d_out layout: [output: B*2D][weights: B*S]

// ---------------------------------------------------------------------------
// Helpers
// ---------------------------------------------------------------------------
__device__ __forceinline__ uint32_t smem_u32(const void* p) {
    uint32_t a;
    asm("{ .reg .u64 t; cvta.to.shared.u64 t, %1; cvt.u32.u64 %0, t; }"
        : "=r"(a) : "l"(p));
    return a;
}
__device__ __forceinline__ void cp_async16(uint32_t dst, const void* src) {
    asm volatile("cp.async.ca.shared.global [%0], [%1], 16;"
                 :: "r"(dst), "l"(src) : "memory");
}
__device__ __forceinline__ void ldsm_x4(uint32_t* r, uint32_t addr) {
    asm volatile("ldmatrix.sync.aligned.m8n8.x4.shared.b16 {%0,%1,%2,%3}, [%4];"
                 : "=r"(r[0]), "=r"(r[1]), "=r"(r[2]), "=r"(r[3]) : "r"(addr));
}
__device__ __forceinline__ void mma16816(float* d, const uint32_t* a,
                                         uint32_t b0, uint32_t b1) {
    asm("mma.sync.aligned.m16n8k16.row.col.f32.f16.f16.f32 "
        "{%0,%1,%2,%3}, {%4,%5,%6,%7}, {%8,%9}, {%0,%1,%2,%3};"
        : "+f"(d[0]), "+f"(d[1]), "+f"(d[2]), "+f"(d[3])
        : "r"(a[0]), "r"(a[1]), "r"(a[2]), "r"(a[3]), "r"(b0), "r"(b1));
}

// ---------------------------------------------------------------------------
// Prep (fused): Bmat[n][k] = M[k][n] = Wq[k,:]·Wk[n,:] -> fp16, n-major.
// Block (0,0) additionally computes c1/c2/c0.
// ---------------------------------------------------------------------------
__global__ void prep_kernel(const float* __restrict__ wq, const float* __restrict__ wk,
                            const float* __restrict__ bq, const float* __restrict__ bk) {
    __shared__ float aS[16][16];
    __shared__ float bS[16][17];
    int tx = threadIdx.x, ty = threadIdx.y;
    int i = blockIdx.y * 16 + ty;   // k index
    int j = blockIdx.x * 16 + tx;   // n index
    float acc = 0.f;
    for (int kt = 0; kt < D; kt += 16) {
        aS[ty][tx] = wq[(blockIdx.y * 16 + ty) * D + kt + tx];
        bS[ty][tx] = wk[(blockIdx.x * 16 + ty) * D + kt + tx];
        __syncthreads();
#pragma unroll
        for (int kk = 0; kk < 16; kk++)
            acc = fmaf(aS[ty][kk], bS[tx][kk], acc);
        __syncthreads();
    }
    g_Bhi[j * D + i] = __float2half_rn(acc);

    if (blockIdx.x == 0 && blockIdx.y == 0) {
        int t = ty * 16 + tx;      // 0..255
        float s1 = 0.f, s2 = 0.f;
#pragma unroll 4
        for (int k = 0; k < D; k++) {
            s1 = fmaf(wq[t * D + k], bk[k], s1);
            s2 = fmaf(wk[t * D + k], bq[k], s2);
        }
        g_vec[t] = s1;
        g_vec[D + t] = s2;
        if (t == 0) {
            float c0 = 0.f;
            for (int k = 0; k < D; k++) c0 = fmaf(bq[k], bk[k], c0);
            g_vec[2 * D] = c0;
        }
    }
}

// ---------------------------------------------------------------------------
// Score kernel: 256 threads, 8 warps (2m x 4n). Warp = 64 rows x 64 cols:
// mt=4, nt=8, acc[4][8][4] = 128 regs with a 255-reg budget (NO occupancy
// pin — spills are worse than serialized phases, measured R15).
// Dyn smem: A [128 x 528B]  B [256 x 528B]
// ---------------------------------------------------------------------------
#define A_PITCH 528
#define B_PITCH 528
#define SM_A 0
#define SM_B (128 * A_PITCH)                   // 67584
#define DSMEM_BYTES (SM_B + 256 * B_PITCH)     // 202752

__global__ __launch_bounds__(256, 1) void score_kernel(const float* __restrict__ vi,
                                                       const float* __restrict__ au) {
    extern __shared__ __align__(16) char dsm[];
    __shared__ float c1_s[D];
    __shared__ float c2_s[D];
    __shared__ float bpart[256];
    __shared__ float spart[4][128];

    const int tid = threadIdx.x;
    const int lane = tid & 31;
    const int w = tid >> 5;
    const int mbase = (w & 1) * 64;        // m-group: 64 rows
    const int ng = w >> 1;                 // n-group 0..3 (64 cols each)
    const int tok0 = blockIdx.x * MTILE;
    const uint32_t sbase = smem_u32(dsm);

    c1_s[tid] = g_vec[tid];
    c2_s[tid] = g_vec[D + tid];
    __syncthreads();

    // ---- Stage B (M^T fp16, 256 rows x 512B) via cp.async
#pragma unroll
    for (int i = 0; i < 32; i++) {
        int idx = tid + i * 256;           // 0..8191 (16B segments)
        int row = idx >> 5, seg = idx & 31;
        cp_async16(sbase + SM_B + row * B_PITCH + seg * 16,
                   g_Bhi + row * D + seg * 8);
    }
    asm volatile("cp.async.commit_group;" ::: "memory");

    // ---- Convert vi (full k) to fp16 in smem (overlaps cp.async); fold vi·c1
    {
        const int r = tid >> 1;            // token row 0..127
        const int kq = (tid & 1) * 128;    // k-range start
        const float* vrow = vi + (size_t)(tok0 + r) * D + kq;
        char* da = dsm + SM_A + r * A_PITCH + kq * 2;
        float bs = 0.f;
#pragma unroll 4
        for (int k8 = 0; k8 < 128; k8 += 8) {
            float4 v0 = *(const float4*)(vrow + k8);
            float4 v1 = *(const float4*)(vrow + k8 + 4);
            float vv[8] = {v0.x, v0.y, v0.z, v0.w, v1.x, v1.y, v1.z, v1.w};
            uint32_t hw[4];
#pragma unroll
            for (int u = 0; u < 4; u++) {
                float a = vv[2 * u], bvl = vv[2 * u + 1];
                bs = fmaf(a, c1_s[kq + k8 + 2 * u], bs);
                bs = fmaf(bvl, c1_s[kq + k8 + 2 * u + 1], bs);
                __half2 hp;
                hp.x = __float2half_rn(a);
                hp.y = __float2half_rn(bvl);
                hw[u] = *(uint32_t*)&hp;
            }
            *(uint4*)(da + k8 * 2) = make_uint4(hw[0], hw[1], hw[2], hw[3]);
        }
        bpart[tid] = bs;
    }
    asm volatile("cp.async.wait_group 0;" ::: "memory");
    __syncthreads();

    // ---- ldmatrix lane addressing
    const uint32_t a_lane = (uint32_t)((lane & 15) * A_PITCH + ((lane >> 4) << 4));
    const uint32_t aA = sbase + SM_A + mbase * A_PITCH + a_lane;
    const uint32_t b_lane =
        (uint32_t)(((lane & 7) + ((lane >> 4) << 3)) * B_PITCH + ((lane & 8) ? 16 : 0));
    const uint32_t bB = sbase + SM_B + ng * 64 * B_PITCH + b_lane;

    float acc[4][8][4] = {};

    // ---- Mainloop: 16 k-steps, 8 LDSM -> 32 MMA per step
#pragma unroll
    for (int ks = 0; ks < 16; ks++) {
        const uint32_t ka = (uint32_t)(ks * 32);   // byte offset (16 k fp16)
        uint32_t ah[4][4];
#pragma unroll
        for (int mt = 0; mt < 4; mt++)
            ldsm_x4(ah[mt], aA + mt * 16 * A_PITCH + ka);
#pragma unroll
        for (int nt2 = 0; nt2 < 4; nt2++) {
            const uint32_t bo = (uint32_t)(nt2 * 16 * B_PITCH) + ka;
            uint32_t b4[4];
            ldsm_x4(b4, bB + bo);
#pragma unroll
            for (int sub = 0; sub < 2; sub++) {
                const int nt = nt2 * 2 + sub;
                const uint32_t b0 = b4[2 * sub], b1 = b4[2 * sub + 1];
#pragma unroll
                for (int mt = 0; mt < 4; mt++)
                    mma16816(acc[mt][nt], ah[mt], b0, b1);
            }
        }
    }

    // ---- Epilogue: part[t] = sum_n (Q'[t][n] + c2[n]) * au[t][n]
    float prow[4][2] = {};
#pragma unroll
    for (int mt = 0; mt < 4; mt++) {
        const float* au0 = au + (size_t)(tok0 + mbase + mt * 16 + (lane >> 2)) * D;
        const float* au1 = au0 + 8 * D;
#pragma unroll
        for (int nt = 0; nt < 8; nt++) {
            const int n = ng * 64 + nt * 8 + (lane & 3) * 2;
            const float2 c2v = *(const float2*)&c2_s[n];
            const float2 x0 = __ldg((const float2*)(au0 + n));
            const float2 x1 = __ldg((const float2*)(au1 + n));
            prow[mt][0] = fmaf(acc[mt][nt][0] + c2v.x, x0.x, prow[mt][0]);
            prow[mt][0] = fmaf(acc[mt][nt][1] + c2v.y, x0.y, prow[mt][0]);
            prow[mt][1] = fmaf(acc[mt][nt][2] + c2v.x, x1.x, prow[mt][1]);
            prow[mt][1] = fmaf(acc[mt][nt][3] + c2v.y, x1.y, prow[mt][1]);
        }
    }
#pragma unroll
    for (int mt = 0; mt < 4; mt++)
#pragma unroll
        for (int j = 0; j < 2; j++) {
            float v = prow[mt][j];
            v += __shfl_xor_sync(0xffffffffu, v, 1);
            v += __shfl_xor_sync(0xffffffffu, v, 2);
            if ((lane & 3) == 0)
                spart[ng][mbase + mt * 16 + j * 8 + (lane >> 2)] = v;
        }
    __syncthreads();

    if (tid < 128) {
        float s = (spart[0][tid] + spart[1][tid]) + (spart[2][tid] + spart[3][tid])
                + (bpart[2 * tid] + bpart[2 * tid + 1])
                + g_vec[2 * D];
        g_score[tok0 + tid] = s;           // raw (scaled in softmax)
    }
}

// ---------------------------------------------------------------------------
// Softmax over S per batch; scales by 1/16, writes weights into d_out.
// ---------------------------------------------------------------------------
__global__ __launch_bounds__(1024) void softmax_kernel(float* __restrict__ out) {
    __shared__ float red[32];
    __shared__ float sh_val;
    const int b = blockIdx.x;
    const int tid = threadIdx.x;
    const int lane = tid & 31, warp = tid >> 5;
    const float* sc = g_score + b * S;
    float* w = out + B * D2 + b * S;

    float v[8];
    float mx = -CUDART_INF_F;
#pragma unroll
    for (int i = 0; i < 8; i++) {
        v[i] = sc[tid + i * 1024] * 0.0625f;   // 1/sqrt(256)
        mx = fmaxf(mx, v[i]);
    }
#pragma unroll
    for (int o = 16; o > 0; o >>= 1) mx = fmaxf(mx, __shfl_xor_sync(0xffffffffu, mx, o));
    if (lane == 0) red[warp] = mx;
    __syncthreads();
    if (warp == 0) {
        float m = red[lane];
#pragma unroll
        for (int o = 16; o > 0; o >>= 1) m = fmaxf(m, __shfl_xor_sync(0xffffffffu, m, o));
        if (lane == 0) sh_val = m;
    }
    __syncthreads();
    mx = sh_val;

    float sum = 0.f;
#pragma unroll
    for (int i = 0; i < 8; i++) {
        v[i] = expf(v[i] - mx);
        sum += v[i];
    }
#pragma unroll
    for (int o = 16; o > 0; o >>= 1) sum += __shfl_xor_sync(0xffffffffu, sum, o);
    if (lane == 0) red[warp] = sum;
    __syncthreads();
    if (warp == 0) {
        float s2 = red[lane];
#pragma unroll
        for (int o = 16; o > 0; o >>= 1) s2 += __shfl_xor_sync(0xffffffffu, s2, o);
        if (lane == 0) sh_val = s2;
    }
    __syncthreads();
    const float inv = 1.f / sh_val;
#pragma unroll
    for (int i = 0; i < 8; i++) w[tid + i * 1024] = v[i] * inv;
}

// ---------------------------------------------------------------------------
// Weighted sum of cat(vi, au): float4 per thread, 4-way S-split, 8-deep unroll.
// ---------------------------------------------------------------------------
__global__ __launch_bounds__(512) void wsum_kernel(const float* __restrict__ vi,
                                                   const float* __restrict__ au,
                                                   const float* __restrict__ out) {
    const int chunk = blockIdx.x;
    const int b = blockIdx.y;
    const int tid = threadIdx.x;
    const int e4 = tid & 127;
    const int sg = tid >> 7;               // 0..3
    const int e = e4 * 4;
    const long row0 = (long)b * S + chunk * SCHUNK + sg * 128;
    const float* w = out + B * D2 + b * S + chunk * SCHUNK + sg * 128;
    const float* src = (e < D) ? (vi + row0 * D + e)
                               : (au + row0 * D + (e - D));
    float4 sa[8];
#pragma unroll
    for (int i = 0; i < 8; i++) sa[i] = make_float4(0.f, 0.f, 0.f, 0.f);
#pragma unroll 1
    for (int s = 0; s < 128; s += 8) {
        float4 vld[8];
        float wl[8];
#pragma unroll
        for (int i = 0; i < 8; i++)
            vld[i] = *(const float4*)(src + (size_t)(s + i) * D);
#pragma unroll
        for (int i = 0; i < 8; i++) wl[i] = w[s + i];
#pragma unroll
        for (int i = 0; i < 8; i++) {
            sa[i].x = fmaf(wl[i], vld[i].x, sa[i].x);
            sa[i].y = fmaf(wl[i], vld[i].y, sa[i].y);
            sa[i].z = fmaf(wl[i], vld[i].z, sa[i].z);
            sa[i].w = fmaf(wl[i], vld[i].w, sa[i].w);
        }
    }
    float4 r;
    r.x = ((sa[0].x + sa[1].x) + (sa[2].x + sa[3].x))
        + ((sa[4].x + sa[5].x) + (sa[6].x + sa[7].x));
    r.y = ((sa[0].y + sa[1].y) + (sa[2].y + sa[3].y))
        + ((sa[4].y + sa[5].y) + (sa[6].y + sa[7].y));
    r.z = ((sa[0].z + sa[1].z) + (sa[2].z + sa[3].z))
        + ((sa[4].z + sa[5].z) + (sa[6].z + sa[7].z));
    r.w = ((sa[0].w + sa[1].w) + (sa[2].w + sa[3].w))
        + ((sa[4].w + sa[5].w) + (sa[6].w + sa[7].w));
    *(float4*)(g_wpart + (size_t)(b * NPART + chunk * 4 + sg) * D2 + e) = r;
}

// ---------------------------------------------------------------------------
// Final: wcat = sum of partials; output = wcat @ Wv + bv.
// Grid (B, 4): block owns 128 e-cols; threads split f into 4 segments.
// ---------------------------------------------------------------------------
__global__ __launch_bounds__(512) void out_kernel(const float* __restrict__ wv_w,
                                                  const float* __restrict__ wv_b,
                                                  float* __restrict__ out) {
    __shared__ float wc[D2];
    __shared__ float red[4][128];
    const int b = blockIdx.x;
    const int ebase = blockIdx.y * 128;
    const int tid = threadIdx.x;

    float a = 0.f;
#pragma unroll 8
    for (int c = 0; c < NPART; c++) a += g_wpart[(size_t)(b * NPART + c) * D2 + tid];
    wc[tid] = a;
    __syncthreads();

    const int e = ebase + (tid & 127);
    const int fs = tid >> 7;               // f-segment 0..3
    float o = 0.f;
#pragma unroll 4
    for (int f = fs * 128; f < fs * 128 + 128; f++)
        o = fmaf(wc[f], wv_w[f * D2 + e], o);
    red[fs][tid & 127] = o;
    __syncthreads();
    if (tid < 128) {
        out[b * D2 + ebase + tid] =
            (red[0][tid] + red[1][tid]) + (red[2][tid] + red[3][tid])
            + wv_b[ebase + tid];
    }
}

// ---------------------------------------------------------------------------
extern "C" void kernel_launch(void* const* d_in, const int* in_sizes, int n_in,
                              void* d_out, int out_size) {
    const float* au   = (const float*)d_in[0];
    const float* vi   = (const float*)d_in[1];
    const float* wq_w = (const float*)d_in[2];
    const float* wq_b = (const float*)d_in[3];
    const float* wk_w = (const float*)d_in[4];
    const float* wk_b = (const float*)d_in[5];
    const float* wv_w = (const float*)d_in[6];
    const float* wv_b = (const float*)d_in[7];
    float* out = (float*)d_out;

    static int smem_set = 0;
    if (!smem_set) {
        cudaFuncSetAttribute(score_kernel, cudaFuncAttributeMaxDynamicSharedMemorySize,
                             DSMEM_BYTES);
        smem_set = 1;
    }

    prep_kernel<<<dim3(16, 16), dim3(16, 16)>>>(wq_w, wk_w, wq_b, wk_b);
    score_kernel<<<NTOK / MTILE, 256, DSMEM_BYTES>>>(vi, au);
    softmax_kernel<<<B, 1024>>>(out);
    wsum_kernel<<<dim3(SCHUNKS, B), 512>>>(vi, au, out);
    out_kernel<<<dim3(B, 4), 512>>>(wv_w, wv_b, out);
}